// round 13
// baseline (speedup 1.0000x reference)
#include <cuda_runtime.h>
#include <cstdint>

// CausalMemoryAttention: B=16, S=4096, D=1024   (exact restructure, validated)
//   Q = query@Wq^T + bq ; qt = Q@Wk ; qbk = query.(Wq^T.bk) + bq.bk
//   score[b,s] = (mb[b,s].qt[b] + qbk[b])/32 * tw[b,s],  tw = exp(-0.01*(ct-ts))
//   p = exp(score); attn = p/E; m = (sum p*mb)/E; attended = m@Wv^T + bv
// 5 launches (k_main deliberately 4th for ncu capture):
//   k_pre (Q partials shuffle-free + tw)                          192 blocks
//   k_u   (u = Wq^T.bk, 16-way d-split)                            64 blocks
//   k_qt  (Q reduce+bias fold -> qt partials, shuffle-free)       128 blocks
//   k_main(268MB pass, R4-validated 3-deep cp.async stage pipeline;
//          last CTA per b -> m and attn normalize)                288 blocks
//   k_post(attended GEMM: hoisted Wv loads, m in smem)            128 blocks

#define B 16
#define S 4096
#define D 1024
#define D4 256
#define QT_SPLITS 16
#define U_SPLITS 16
#define CTAS_PER_B 18
#define NCTA_MAIN (B * CTAS_PER_B)        // 288 (single wave at 2 CTA/SM)
#define DEPTH 3
#define STAGE_ROWS 8
#define STAGE_F4 (STAGE_ROWS * D4)        // 2048 float4
#define STAGE_BYTES (STAGE_F4 * 16)       // 32 KB
#define SMEM_MAIN (DEPTH * STAGE_BYTES)   // 96 KB
#define SMEM_POST (B * D * 4)             // 64 KB (all of m)

// -------- scratch (device globals; counter self-resets) --------
__device__ __align__(16) float g_q_part[16 * B * D];     // c-split Q partials
__device__ __align__(16) float g_qt_part[QT_SPLITS * B * D];
__device__ __align__(16) float g_u_part[U_SPLITS * D];
__device__ __align__(16) float g_tw[B * S];
__device__ __align__(16) float g_p[B * S];
__device__ __align__(16) float g_macc[NCTA_MAIN * D];
__device__ float g_Epart[NCTA_MAIN];
__device__ __align__(16) float g_m[B * D];
__device__ int g_cnt[B];      // k_main CTAs done per b (arrive-only, no spin)

// ---------------- cp.async helpers ----------------
__device__ __forceinline__ void cp_async16(uint32_t smem, const void* gmem) {
    asm volatile("cp.async.cg.shared.global [%0], [%1], 16;"
                 :: "r"(smem), "l"(gmem) : "memory");
}
__device__ __forceinline__ void cp_commit() {
    asm volatile("cp.async.commit_group;" ::: "memory");
}
template <int N> __device__ __forceinline__ void cp_wait() {
    asm volatile("cp.async.wait_group %0;" :: "n"(N) : "memory");
}

// ============================================================
// k_pre: 192 independent blocks x 256 threads. Shuffle-free.
//   bid 0..127 : Q-partial role. block = (d-tile 128, c-chunk 64).
//     Wq tile transposed in smem (pad 133), query chunk in smem;
//     thread owns one d-column x 8 batches. -> g_q_part[cs][b][d]
//   bid 128..191: tw-role. tw = exp(-0.01*(ct-ts)).
// ============================================================
__global__ __launch_bounds__(256) void k_pre(
    const float* __restrict__ query, const float* __restrict__ Wq,
    const float* __restrict__ ts, const float* __restrict__ ct)
{
    int bid = blockIdx.x, tid = threadIdx.x;

    if (bid < 128) {
        __shared__ float wt[64 * 133];    // wt[c][d_local], pad 133
        __shared__ float qs[16 * 64];     // qs[b][c]
        int dt = bid & 7, cs = bid >> 3;
        int d0 = dt * 128, c0 = cs * 64;

#pragma unroll
        for (int i = 0; i < 32; i++) {
            int row = i * 4 + (tid >> 6);   // d_local 0..127
            int col = tid & 63;             // c_local 0..63
            wt[col * 133 + row] = Wq[(size_t)(d0 + row) * D + c0 + col];
        }
        for (int i = tid; i < 1024; i += 256) {
            int b = i >> 6, c = i & 63;
            qs[b * 64 + c] = query[b * D + c0 + c];
        }
        __syncthreads();

        int dl = tid & 127;
        int bh = tid >> 7;                  // 0/1 -> batches 0..7 / 8..15
        float acc[8];
#pragma unroll
        for (int bb = 0; bb < 8; bb++) acc[bb] = 0.f;
#pragma unroll 4
        for (int c = 0; c < 64; c++) {
            float wv = wt[c * 133 + dl];
#pragma unroll
            for (int bb = 0; bb < 8; bb++)
                acc[bb] += qs[(bh * 8 + bb) * 64 + c] * wv;
        }
#pragma unroll
        for (int bb = 0; bb < 8; bb++)
            g_q_part[(size_t)cs * (B * D) + (bh * 8 + bb) * D + d0 + dl] = acc[bb];
    } else {
        // tw-role
        int idx = (bid - 128) * 1024 + tid * 4;
        int b = idx >> 12;
        float curt = ct[b];
        float4 t = *reinterpret_cast<const float4*>(ts + idx);
        float4 w;
        w.x = __expf(-0.01f * (curt - t.x));
        w.y = __expf(-0.01f * (curt - t.y));
        w.z = __expf(-0.01f * (curt - t.z));
        w.w = __expf(-0.01f * (curt - t.w));
        *reinterpret_cast<float4*>(g_tw + idx) = w;
    }
}

// ============================================================
// k_u: 64 blocks x 256 threads. u[e] partial over 64-d chunk (MLP 16).
// ============================================================
__global__ __launch_bounds__(256) void k_u(
    const float* __restrict__ Wq, const float* __restrict__ bk)
{
    int q = blockIdx.x;
    int e = (q & 3) * 256 + threadIdx.x;
    int dp = q >> 2;                    // 0..15
    int dbase = dp * 64;
    float s = 0.f;
#pragma unroll 16
    for (int d = 0; d < 64; d++)
        s += Wq[(size_t)(dbase + d) * D + e] * bk[dbase + d];
    g_u_part[dp * D + e] = s;
}

// ============================================================
// k_qt: 128 blocks x 128 threads. Shuffle-free.
//   block = (e-tile 128, d-chunk 64). On load: Q[b,d] = sum of 16
//   c-split partials + bq[d] -> smem Qs[dl][b] (pad 20). Thread per e:
//   64 x 16 FMA against coalesced Wk (unroll 8). -> g_qt_part[by][b][e]
// ============================================================
__global__ __launch_bounds__(128) void k_qt(
    const float* __restrict__ Wk, const float* __restrict__ bq)
{
    __shared__ float Qs[64 * 20];      // Qs[dl][b], pad 20
    int et = blockIdx.x & 7, by = blockIdx.x >> 3;
    int e = et * 128 + threadIdx.x;
    int d0 = by * 64;

    for (int i = threadIdx.x; i < 1024; i += 128) {
        int dl = i & 63, b = i >> 6;
        float s = bq[d0 + dl];
#pragma unroll
        for (int sp = 0; sp < 16; sp++)
            s += g_q_part[(size_t)sp * (B * D) + b * D + d0 + dl];
        Qs[dl * 20 + b] = s;
    }
    __syncthreads();

    float acc[16];
#pragma unroll
    for (int bb = 0; bb < 16; bb++) acc[bb] = 0.f;
#pragma unroll 8
    for (int dl = 0; dl < 64; dl++) {
        float wv = Wk[(size_t)(d0 + dl) * D + e];
        const float4* q4 = reinterpret_cast<const float4*>(&Qs[dl * 20]);
#pragma unroll
        for (int j = 0; j < 4; j++) {
            float4 qq = q4[j];
            acc[4 * j + 0] += qq.x * wv;
            acc[4 * j + 1] += qq.y * wv;
            acc[4 * j + 2] += qq.z * wv;
            acc[4 * j + 3] += qq.w * wv;
        }
    }
#pragma unroll
    for (int bb = 0; bb < 16; bb++)
        g_qt_part[(size_t)(by * 16 + bb) * D + e] = acc[bb];
}

// ============================================================
// k_main: streaming pass over memory_bank. R4-VALIDATED loop:
// prologue issues stages 0,1,2 (3 in flight); iter i: wait<DEPTH-1>
// -> sync -> v[] regs -> sync -> refill slot i%3 with stage i+3
// -> compute. Measured 54.3us @ 62% DRAM in R4.
// Last CTA per b finalizes m = (sum macc)/E and normalizes attn[b,:].
// ============================================================
__global__ __launch_bounds__(256, 2) void k_main(
    const float* __restrict__ mb, const float* __restrict__ query,
    const float* __restrict__ bq, const float* __restrict__ bk,
    float* __restrict__ attn)
{
    extern __shared__ __align__(16) float4 sbuf[];   // DEPTH * STAGE_F4
    __shared__ float sE[8];
    __shared__ int sLast;

    int b = blockIdx.x / CTAS_PER_B;
    int j = blockIdx.x % CTAS_PER_B;
    int warp = threadIdx.x >> 5, lane = threadIdx.x & 31, tid = threadIdx.x;

    // 512 stages per batch split 8x29 + 10x28
    int nst = (j < 8) ? 29 : 28;
    int st0 = (j < 8) ? j * 29 : 232 + (j - 8) * 28;

    const float* gsrc = mb + (size_t)b * S * D + (size_t)st0 * STAGE_ROWS * D;
    uint32_t sb = (uint32_t)__cvta_generic_to_shared(sbuf);

    // ---- prologue: issue first DEPTH stages ----
    int issued = 0;
    for (; issued < DEPTH && issued < nst; issued++) {
        uint32_t dst = sb + (uint32_t)(issued % DEPTH) * STAGE_BYTES;
        const float* src = gsrc + (size_t)issued * STAGE_ROWS * D;
        for (int c = tid; c < STAGE_F4; c += 256)
            cp_async16(dst + (uint32_t)c * 16, src + (size_t)c * 4);
        cp_commit();
    }

    // ---- qt split-reduce (overlaps DRAM ramp) ----
    float4 q[8];
#pragma unroll
    for (int k = 0; k < 8; k++) q[k] = make_float4(0.f, 0.f, 0.f, 0.f);
    for (int sp = 0; sp < QT_SPLITS; sp++) {
        const float4* qp = reinterpret_cast<const float4*>(g_qt_part)
                           + (size_t)(sp * B + b) * D4;
#pragma unroll
        for (int k = 0; k < 8; k++) {
            float4 v = qp[k * 32 + lane];
            q[k].x += v.x; q[k].y += v.y; q[k].z += v.z; q[k].w += v.w;
        }
    }
    // ---- qbk = query[b].u + bq.bk  (u = Wq^T.bk, 16 partials) ----
    const float4* X4 = reinterpret_cast<const float4*>(query) + b * D4;
    const float4* U4 = reinterpret_cast<const float4*>(g_u_part);
    const float4* bq4 = reinterpret_cast<const float4*>(bq);
    const float4* bk4 = reinterpret_cast<const float4*>(bk);
    float qb = 0.f;
#pragma unroll
    for (int k = 0; k < 8; k++) {
        int idx = k * 32 + lane;
        float4 u = U4[idx];
#pragma unroll
        for (int sp = 1; sp < U_SPLITS; sp++) {
            float4 up = U4[sp * D4 + idx];
            u.x += up.x; u.y += up.y; u.z += up.z; u.w += up.w;
        }
        float4 x = X4[idx];
        qb += x.x * u.x + x.y * u.y + x.z * u.z + x.w * u.w;
        float4 a = bq4[idx], c = bk4[idx];
        qb += a.x * c.x + a.y * c.y + a.z * c.z + a.w * c.w;
    }
#pragma unroll
    for (int o = 16; o > 0; o >>= 1) qb += __shfl_xor_sync(0xffffffffu, qb, o);

    float4 acc[8];
#pragma unroll
    for (int k = 0; k < 8; k++) acc[k] = make_float4(0.f, 0.f, 0.f, 0.f);
    float Ew = 0.f;

    // ---- mainloop (R4-validated): wait<2> / sync / read / sync / refill ----
    for (int i = 0; i < nst; i++) {
        int s = (st0 + i) * STAGE_ROWS + warp;
        float twv = g_tw[b * S + s];          // off the critical chain

        if (issued < nst) cp_wait<DEPTH - 1>(); else cp_wait<0>();
        __syncthreads();

        const float4* vp = sbuf + ((size_t)(i % DEPTH) * STAGE_ROWS + warp) * D4;
        float4 v[8];
#pragma unroll
        for (int k = 0; k < 8; k++) v[k] = vp[k * 32 + lane];
        __syncthreads();                 // slot consumed -> free for refill

        // refill the freed slot BEFORE the long compute chain
        if (issued < nst) {
            uint32_t dst = sb + (uint32_t)(issued % DEPTH) * STAGE_BYTES;
            const float* src = gsrc + (size_t)issued * STAGE_ROWS * D;
            for (int c = tid; c < STAGE_F4; c += 256)
                cp_async16(dst + (uint32_t)c * 16, src + (size_t)c * 4);
            cp_commit();
            issued++;
        }

        float d0 = 0.f, d1 = 0.f, d2 = 0.f, d3 = 0.f;
#pragma unroll
        for (int k = 0; k < 8; k++) {
            d0 += v[k].x * q[k].x; d1 += v[k].y * q[k].y;
            d2 += v[k].z * q[k].z; d3 += v[k].w * q[k].w;
        }
        float ds = (d0 + d1) + (d2 + d3);
#pragma unroll
        for (int o = 16; o > 0; o >>= 1) ds += __shfl_xor_sync(0xffffffffu, ds, o);

        float p = __expf((ds + qb) * 0.03125f * twv);
        if (lane == 0) g_p[b * S + s] = p;
        Ew += p;
#pragma unroll
        for (int k = 0; k < 8; k++) {
            acc[k].x += p * v[k].x; acc[k].y += p * v[k].y;
            acc[k].z += p * v[k].z; acc[k].w += p * v[k].w;
        }
    }

    // ---- epilogue: cross-warp reduce (wait for last refill, reuse sbuf) ----
    cp_wait<0>();
    __syncthreads();
    float4* red = sbuf;
#pragma unroll
    for (int k = 0; k < 8; k++)
        red[(size_t)warp * D4 + k * 32 + lane] = acc[k];
    if (lane == 0) sE[warp] = Ew;
    __syncthreads();

    float4 r = red[tid];
#pragma unroll
    for (int w = 1; w < 8; w++) {
        float4 v = red[(size_t)w * D4 + tid];
        r.x += v.x; r.y += v.y; r.z += v.z; r.w += v.w;
    }
    reinterpret_cast<float4*>(g_macc)[(size_t)blockIdx.x * D4 + tid] = r;
    if (tid == 0) {
        float e = 0.f;
#pragma unroll
        for (int w = 0; w < 8; w++) e += sE[w];
        g_Epart[blockIdx.x] = e;
    }

    // ---- last CTA per b: m = (sum macc)/E ; attn[b,:] = p/E (arrive-only) ----
    __threadfence();
    __syncthreads();
    if (tid == 0) sLast = (atomicAdd(&g_cnt[b], 1) == CTAS_PER_B - 1);
    __syncthreads();
    if (sLast) {
        __threadfence();
        const float4* mp = reinterpret_cast<const float4*>(g_macc);
        float4 a = make_float4(0.f, 0.f, 0.f, 0.f);
#pragma unroll
        for (int c = 0; c < CTAS_PER_B; c++) {
            float4 v = mp[(size_t)(b * CTAS_PER_B + c) * D4 + tid];
            a.x += v.x; a.y += v.y; a.z += v.z; a.w += v.w;
        }
        float Et = 0.f;
#pragma unroll
        for (int c = 0; c < CTAS_PER_B; c++) Et += g_Epart[b * CTAS_PER_B + c];
        float inv = 1.f / Et;
        a.x *= inv; a.y *= inv; a.z *= inv; a.w *= inv;
        reinterpret_cast<float4*>(g_m)[b * D4 + tid] = a;

        const float4* pp = reinterpret_cast<const float4*>(g_p + b * S);
        float4* ap = reinterpret_cast<float4*>(attn + b * S);
#pragma unroll
        for (int it = 0; it < 4; it++) {
            float4 p = pp[it * 256 + tid];
            p.x *= inv; p.y *= inv; p.z *= inv; p.w *= inv;
            ap[it * 256 + tid] = p;
        }
        if (tid == 0) g_cnt[b] = 0;
    }
}

// ============================================================
// k_post: 128 blocks x 256 threads. attended[b,d] = m[b].Wv[d] + bv[d].
// All 8 Wv float4 loads issued FIRST (8 independent DRAM transactions),
// then m (64KB) staged in smem under them; 16 independent batch
// accumulators; ONE shuffle-reduce phase.
// ============================================================
__global__ __launch_bounds__(256) void k_post(
    const float* __restrict__ Wv, const float* __restrict__ bv,
    float* __restrict__ attended)
{
    extern __shared__ __align__(16) float4 ms4[];   // [B][256] = 64 KB
    int tid = threadIdx.x;
    int warp = tid >> 5, lane = tid & 31;
    int d = blockIdx.x * 8 + warp;

    // hoist Wv row loads: 8 independent coalesced 512B warp transactions
    const float4* W4 = reinterpret_cast<const float4*>(Wv) + (size_t)d * D4;
    float4 w[8];
#pragma unroll
    for (int ch = 0; ch < 8; ch++) w[ch] = W4[ch * 32 + lane];

    // stage m while Wv loads are in flight
    const float4* gm4 = reinterpret_cast<const float4*>(g_m);
    for (int i = tid; i < B * D4; i += 256) ms4[i] = gm4[i];
    __syncthreads();

    float acc[16];
#pragma unroll
    for (int bb = 0; bb < 16; bb++) acc[bb] = 0.f;

#pragma unroll
    for (int ch = 0; ch < 8; ch++) {
#pragma unroll
        for (int bb = 0; bb < 16; bb++) {
            float4 m = ms4[bb * D4 + ch * 32 + lane];
            acc[bb] += m.x * w[ch].x + m.y * w[ch].y
                     + m.z * w[ch].z + m.w * w[ch].w;
        }
    }

    // one reduce phase: 16 independent xor trees (interleaved for ILP)
#pragma unroll
    for (int o = 16; o > 0; o >>= 1) {
#pragma unroll
        for (int bb = 0; bb < 16; bb++)
            acc[bb] += __shfl_xor_sync(0xffffffffu, acc[bb], o);
    }
    if (lane == 0) {
        float bb_ = bv[d];
#pragma unroll
        for (int bb = 0; bb < 16; bb++)
            attended[bb * D + d] = acc[bb] + bb_;
    }
}

// ============================================================
extern "C" void kernel_launch(void* const* d_in, const int* in_sizes, int n_in,
                              void* d_out, int out_size)
{
    const float* query = (const float*)d_in[0];
    const float* mb    = (const float*)d_in[1];
    const float* ts    = (const float*)d_in[2];
    const float* ct    = (const float*)d_in[3];
    const float* Wq    = (const float*)d_in[4];
    const float* bq    = (const float*)d_in[5];
    const float* Wk    = (const float*)d_in[6];
    const float* bk    = (const float*)d_in[7];
    const float* Wv    = (const float*)d_in[8];
    const float* bv    = (const float*)d_in[9];
    (void)in_sizes; (void)n_in; (void)out_size;

    float* attended = (float*)d_out;            // [16,1024]
    float* attn     = (float*)d_out + B * D;    // [16,4096]

    cudaFuncSetAttribute(k_main, cudaFuncAttributeMaxDynamicSharedMemorySize,
                         SMEM_MAIN);
    cudaFuncSetAttribute(k_post, cudaFuncAttributeMaxDynamicSharedMemorySize,
                         SMEM_POST);

    k_pre<<<192, 256>>>(query, Wq, ts, ct);                   // 1: Q parts + tw
    k_u<<<64, 256>>>(Wq, bk);                                 // 2: u partials
    k_qt<<<128, 128>>>(Wk, bq);                               // 3: qt partials
    k_main<<<NCTA_MAIN, 256, SMEM_MAIN>>>(mb, query, bq, bk, attn); // 4: 268MB
    k_post<<<128, 256, SMEM_POST>>>(Wv, bv, attended);        // 5: attended
}

// round 14
// speedup vs baseline: 1.2214x; 1.2214x over previous
#include <cuda_runtime.h>
#include <cstdint>

// CausalMemoryAttention: B=16, S=4096, D=1024   (exact restructure, validated)
//   Q = query@Wq^T + bq ; qt = Q@Wk ; qbk = query.(Wq^T.bk) + bq.bk
//   score[b,s] = (mb[b,s].qt[b] + qbk[b])/32 * tw[b,s],  tw = exp(-0.01*(ct-ts))
//   p = exp(score); attn = p/E; m = (sum p*mb)/E; attended = m@Wv^T + bv
// 6 launches (k_main deliberately 4th for ncu capture):
//   k_pre (Q partials + u partials + tw)                          256 blocks
//   k_qbk (qbk[b] = query[b].u + bq.bk)                            16 blocks
//   k_qt  (Q reduce+bias fold -> qt partials)                     128 blocks
//   k_main(268MB pass, R4 loop, SLIM prologue/epilogue, no fusion) 288 blocks
//   k_mid (E; m = sum macc / E; attn = p/E)                        80 blocks
//   k_post(attended GEMM, hoisted Wv loads)                       128 blocks

#define B 16
#define S 4096
#define D 1024
#define D4 256
#define QT_SPLITS 16
#define U_SPLITS 16
#define CTAS_PER_B 18
#define NCTA_MAIN (B * CTAS_PER_B)        // 288 (single wave at 2 CTA/SM)
#define DEPTH 3
#define STAGE_ROWS 8
#define STAGE_F4 (STAGE_ROWS * D4)        // 2048 float4
#define STAGE_BYTES (STAGE_F4 * 16)       // 32 KB
#define SMEM_MAIN (DEPTH * STAGE_BYTES)   // 96 KB
#define SMEM_POST (B * D * 4)             // 64 KB (all of m)

// -------- scratch (device globals; no dynamic allocation) --------
__device__ __align__(16) float g_q_part[16 * B * D];     // c-split Q partials
__device__ __align__(16) float g_qt_part[QT_SPLITS * B * D];
__device__ __align__(16) float g_u_part[U_SPLITS * D];
__device__ float g_qbk[B];
__device__ __align__(16) float g_tw[B * S];
__device__ __align__(16) float g_p[B * S];
__device__ __align__(16) float g_macc[NCTA_MAIN * D];
__device__ float g_Epart[NCTA_MAIN];
__device__ __align__(16) float g_m[B * D];

// ---------------- cp.async helpers ----------------
__device__ __forceinline__ void cp_async16(uint32_t smem, const void* gmem) {
    asm volatile("cp.async.cg.shared.global [%0], [%1], 16;"
                 :: "r"(smem), "l"(gmem) : "memory");
}
__device__ __forceinline__ void cp_commit() {
    asm volatile("cp.async.commit_group;" ::: "memory");
}
template <int N> __device__ __forceinline__ void cp_wait() {
    asm volatile("cp.async.wait_group %0;" :: "n"(N) : "memory");
}

// ============================================================
// k_pre: 256 independent blocks x 256 threads. Shuffle-free.
//   bid 0..127 : Q-partial role (d-tile 128, c-chunk 64) -> g_q_part
//   bid 128..191: u-role (e-tile 256, d-chunk 64, MLP 16) -> g_u_part
//   bid 192..255: tw-role.
// ============================================================
__global__ __launch_bounds__(256) void k_pre(
    const float* __restrict__ query, const float* __restrict__ Wq,
    const float* __restrict__ bk,
    const float* __restrict__ ts, const float* __restrict__ ct)
{
    int bid = blockIdx.x, tid = threadIdx.x;

    if (bid < 128) {
        __shared__ float wt[64 * 133];    // wt[c][d_local], pad 133
        __shared__ float qs[16 * 64];     // qs[b][c]
        int dt = bid & 7, cs = bid >> 3;
        int d0 = dt * 128, c0 = cs * 64;

#pragma unroll
        for (int i = 0; i < 32; i++) {
            int row = i * 4 + (tid >> 6);   // d_local 0..127
            int col = tid & 63;             // c_local 0..63
            wt[col * 133 + row] = Wq[(size_t)(d0 + row) * D + c0 + col];
        }
        for (int i = tid; i < 1024; i += 256) {
            int b = i >> 6, c = i & 63;
            qs[b * 64 + c] = query[b * D + c0 + c];
        }
        __syncthreads();

        int dl = tid & 127;
        int bh = tid >> 7;                  // 0/1 -> batches 0..7 / 8..15
        float acc[8];
#pragma unroll
        for (int bb = 0; bb < 8; bb++) acc[bb] = 0.f;
#pragma unroll 4
        for (int c = 0; c < 64; c++) {
            float wv = wt[c * 133 + dl];
#pragma unroll
            for (int bb = 0; bb < 8; bb++)
                acc[bb] += qs[(bh * 8 + bb) * 64 + c] * wv;
        }
#pragma unroll
        for (int bb = 0; bb < 8; bb++)
            g_q_part[(size_t)cs * (B * D) + (bh * 8 + bb) * D + d0 + dl] = acc[bb];
    } else if (bid < 192) {
        // u-role: u[e] partial over 64 d's, unroll 16 (MLP 16)
        int q = bid - 128;
        int e = (q & 3) * 256 + tid;
        int dp = q >> 2;                    // 0..15
        int dbase = dp * 64;
        float s = 0.f;
#pragma unroll 16
        for (int d = 0; d < 64; d++)
            s += Wq[(size_t)(dbase + d) * D + e] * bk[dbase + d];
        g_u_part[dp * D + e] = s;
    } else {
        // tw-role
        int idx = (bid - 192) * 1024 + tid * 4;
        int b = idx >> 12;
        float curt = ct[b];
        float4 t = *reinterpret_cast<const float4*>(ts + idx);
        float4 w;
        w.x = __expf(-0.01f * (curt - t.x));
        w.y = __expf(-0.01f * (curt - t.y));
        w.z = __expf(-0.01f * (curt - t.z));
        w.w = __expf(-0.01f * (curt - t.w));
        *reinterpret_cast<float4*>(g_tw + idx) = w;
    }
}

// ============================================================
// k_qbk: 16 blocks x 256 threads. qbk[b] = query[b].u + bq.bk
// (u summed from 16 partials on the fly; block reduce via smem+shfl).
// ============================================================
__global__ __launch_bounds__(256) void k_qbk(
    const float* __restrict__ query, const float* __restrict__ bq,
    const float* __restrict__ bk)
{
    __shared__ float sW[8];
    int b = blockIdx.x, tid = threadIdx.x;
    int warp = tid >> 5, lane = tid & 31;

    const float4* U4 = reinterpret_cast<const float4*>(g_u_part);
    const float4* X4 = reinterpret_cast<const float4*>(query) + b * D4;
    const float4* bq4 = reinterpret_cast<const float4*>(bq);
    const float4* bk4 = reinterpret_cast<const float4*>(bk);

    float4 u = U4[tid];
#pragma unroll
    for (int sp = 1; sp < U_SPLITS; sp++) {
        float4 up = U4[sp * D4 + tid];
        u.x += up.x; u.y += up.y; u.z += up.z; u.w += up.w;
    }
    float4 x = X4[tid];
    float s = x.x * u.x + x.y * u.y + x.z * u.z + x.w * u.w;
    float4 a = bq4[tid], c = bk4[tid];
    s += (a.x * c.x + a.y * c.y + a.z * c.z + a.w * c.w) * (1.f / 16.f);
    // (bq.bk split evenly across 16 blocks' worth? No — each block b needs the
    //  FULL bq.bk. tid covers all 256 float4 of bq/bk once per block, so the
    //  full dot is accumulated here; no scaling needed.)
    s += (a.x * c.x + a.y * c.y + a.z * c.z + a.w * c.w) * (15.f / 16.f);

#pragma unroll
    for (int o = 16; o > 0; o >>= 1) s += __shfl_xor_sync(0xffffffffu, s, o);
    if (lane == 0) sW[warp] = s;
    __syncthreads();
    if (warp == 0) {
        float e = (lane < 8) ? sW[lane] : 0.f;
#pragma unroll
        for (int o = 4; o > 0; o >>= 1) e += __shfl_xor_sync(0xffffffffu, e, o);
        if (lane == 0) g_qbk[b] = e;
    }
}

// ============================================================
// k_qt: 128 blocks x 128 threads. Shuffle-free.
//   block = (e-tile 128, d-chunk 64). On load: Q[b,d] = sum of 16
//   c-split partials + bq[d] -> smem Qs[dl][b] (pad 20). Thread per e:
//   64 x 16 FMA against coalesced Wk (unroll 8). -> g_qt_part[by][b][e]
// ============================================================
__global__ __launch_bounds__(128) void k_qt(
    const float* __restrict__ Wk, const float* __restrict__ bq)
{
    __shared__ float Qs[64 * 20];      // Qs[dl][b], pad 20
    int et = blockIdx.x & 7, by = blockIdx.x >> 3;
    int e = et * 128 + threadIdx.x;
    int d0 = by * 64;

    for (int i = threadIdx.x; i < 1024; i += 128) {
        int dl = i & 63, b = i >> 6;
        float s = bq[d0 + dl];
#pragma unroll
        for (int sp = 0; sp < 16; sp++)
            s += g_q_part[(size_t)sp * (B * D) + b * D + d0 + dl];
        Qs[dl * 20 + b] = s;
    }
    __syncthreads();

    float acc[16];
#pragma unroll
    for (int bb = 0; bb < 16; bb++) acc[bb] = 0.f;
#pragma unroll 8
    for (int dl = 0; dl < 64; dl++) {
        float wv = Wk[(size_t)(d0 + dl) * D + e];
        const float4* q4 = reinterpret_cast<const float4*>(&Qs[dl * 20]);
#pragma unroll
        for (int j = 0; j < 4; j++) {
            float4 qq = q4[j];
            acc[4 * j + 0] += qq.x * wv;
            acc[4 * j + 1] += qq.y * wv;
            acc[4 * j + 2] += qq.z * wv;
            acc[4 * j + 3] += qq.w * wv;
        }
    }
#pragma unroll
    for (int bb = 0; bb < 16; bb++)
        g_qt_part[(size_t)(by * 16 + bb) * D + e] = acc[bb];
}

// ============================================================
// k_main: streaming pass over memory_bank. R4-validated loop AND
// R4-slim prologue/epilogue: qbk is a single scalar load; epilogue
// writes macc/Epart only. No atomics, no fences, no fused finalize.
// Target: regs ~118 (below the 128 cap), no spills.
// ============================================================
__global__ __launch_bounds__(256, 2) void k_main(
    const float* __restrict__ mb)
{
    extern __shared__ __align__(16) float4 sbuf[];   // DEPTH * STAGE_F4
    __shared__ float sE[8];

    int b = blockIdx.x / CTAS_PER_B;
    int j = blockIdx.x % CTAS_PER_B;
    int warp = threadIdx.x >> 5, lane = threadIdx.x & 31, tid = threadIdx.x;

    // 512 stages per batch split 8x29 + 10x28
    int nst = (j < 8) ? 29 : 28;
    int st0 = (j < 8) ? j * 29 : 232 + (j - 8) * 28;

    const float* gsrc = mb + (size_t)b * S * D + (size_t)st0 * STAGE_ROWS * D;
    uint32_t sb = (uint32_t)__cvta_generic_to_shared(sbuf);

    // ---- prologue: issue first DEPTH stages ----
    int issued = 0;
    for (; issued < DEPTH && issued < nst; issued++) {
        uint32_t dst = sb + (uint32_t)(issued % DEPTH) * STAGE_BYTES;
        const float* src = gsrc + (size_t)issued * STAGE_ROWS * D;
        for (int c = tid; c < STAGE_F4; c += 256)
            cp_async16(dst + (uint32_t)c * 16, src + (size_t)c * 4);
        cp_commit();
    }

    // ---- qt split-reduce (overlaps DRAM ramp) + qbk scalar ----
    float4 q[8];
#pragma unroll
    for (int k = 0; k < 8; k++) q[k] = make_float4(0.f, 0.f, 0.f, 0.f);
    for (int sp = 0; sp < QT_SPLITS; sp++) {
        const float4* qp = reinterpret_cast<const float4*>(g_qt_part)
                           + (size_t)(sp * B + b) * D4;
#pragma unroll
        for (int k = 0; k < 8; k++) {
            float4 v = qp[k * 32 + lane];
            q[k].x += v.x; q[k].y += v.y; q[k].z += v.z; q[k].w += v.w;
        }
    }
    float qb = g_qbk[b];

    float4 acc[8];
#pragma unroll
    for (int k = 0; k < 8; k++) acc[k] = make_float4(0.f, 0.f, 0.f, 0.f);
    float Ew = 0.f;

    // ---- mainloop (R4-validated): wait<2> / sync / read / sync / refill ----
    for (int i = 0; i < nst; i++) {
        int s = (st0 + i) * STAGE_ROWS + warp;
        float twv = g_tw[b * S + s];          // off the critical chain

        if (issued < nst) cp_wait<DEPTH - 1>(); else cp_wait<0>();
        __syncthreads();

        const float4* vp = sbuf + ((size_t)(i % DEPTH) * STAGE_ROWS + warp) * D4;
        float4 v[8];
#pragma unroll
        for (int k = 0; k < 8; k++) v[k] = vp[k * 32 + lane];
        __syncthreads();                 // slot consumed -> free for refill

        // refill the freed slot BEFORE the long compute chain
        if (issued < nst) {
            uint32_t dst = sb + (uint32_t)(issued % DEPTH) * STAGE_BYTES;
            const float* src = gsrc + (size_t)issued * STAGE_ROWS * D;
            for (int c = tid; c < STAGE_F4; c += 256)
                cp_async16(dst + (uint32_t)c * 16, src + (size_t)c * 4);
            cp_commit();
            issued++;
        }

        float d0 = 0.f, d1 = 0.f, d2 = 0.f, d3 = 0.f;
#pragma unroll
        for (int k = 0; k < 8; k++) {
            d0 += v[k].x * q[k].x; d1 += v[k].y * q[k].y;
            d2 += v[k].z * q[k].z; d3 += v[k].w * q[k].w;
        }
        float ds = (d0 + d1) + (d2 + d3);
#pragma unroll
        for (int o = 16; o > 0; o >>= 1) ds += __shfl_xor_sync(0xffffffffu, ds, o);

        float p = __expf((ds + qb) * 0.03125f * twv);
        if (lane == 0) g_p[b * S + s] = p;
        Ew += p;
#pragma unroll
        for (int k = 0; k < 8; k++) {
            acc[k].x += p * v[k].x; acc[k].y += p * v[k].y;
            acc[k].z += p * v[k].z; acc[k].w += p * v[k].w;
        }
    }

    // ---- epilogue (R4): cross-warp reduce, write macc/Epart, exit ----
    cp_wait<0>();
    __syncthreads();
    float4* red = sbuf;
#pragma unroll
    for (int k = 0; k < 8; k++)
        red[(size_t)warp * D4 + k * 32 + lane] = acc[k];
    if (lane == 0) sE[warp] = Ew;
    __syncthreads();

    float4 r = red[tid];
#pragma unroll
    for (int w = 1; w < 8; w++) {
        float4 v = red[(size_t)w * D4 + tid];
        r.x += v.x; r.y += v.y; r.z += v.z; r.w += v.w;
    }
    reinterpret_cast<float4*>(g_macc)[(size_t)blockIdx.x * D4 + tid] = r;
    if (tid == 0) {
        float e = 0.f;
#pragma unroll
        for (int w = 0; w < 8; w++) e += sE[w];
        g_Epart[blockIdx.x] = e;
    }
}

// ============================================================
// k_mid: 80 blocks. block = (role, b):
//   role 0   : m[b] = (sum_c macc[b,c]) / E
//   role 1..4: attn[b, (role-1)*1024 .. ] = p * (1/E)
// Every block redundantly computes E from the 18 partials (deterministic).
// ============================================================
__global__ __launch_bounds__(256) void k_mid(float* __restrict__ attn)
{
    __shared__ float sInv;
    int b = blockIdx.x & 15;
    int role = blockIdx.x >> 4;        // 0..4
    int tid = threadIdx.x, lane = tid & 31;

    if (tid < 32) {
        float e = (lane < CTAS_PER_B) ? g_Epart[b * CTAS_PER_B + lane] : 0.f;
#pragma unroll
        for (int o = 16; o > 0; o >>= 1) e += __shfl_xor_sync(0xffffffffu, e, o);
        if (lane == 0) sInv = 1.f / e;
    }
    __syncthreads();
    float inv = sInv;

    if (role == 0) {
        const float4* mp = reinterpret_cast<const float4*>(g_macc);
        float4 a = make_float4(0.f, 0.f, 0.f, 0.f);
#pragma unroll
        for (int c = 0; c < CTAS_PER_B; c++) {
            float4 v = mp[(size_t)(b * CTAS_PER_B + c) * D4 + tid];
            a.x += v.x; a.y += v.y; a.z += v.z; a.w += v.w;
        }
        a.x *= inv; a.y *= inv; a.z *= inv; a.w *= inv;
        reinterpret_cast<float4*>(g_m)[b * D4 + tid] = a;
    } else {
        int s = (role - 1) * 1024 + tid * 4;
        float4 p = *reinterpret_cast<const float4*>(g_p + b * S + s);
        p.x *= inv; p.y *= inv; p.z *= inv; p.w *= inv;
        *reinterpret_cast<float4*>(attn + b * S + s) = p;
    }
}

// ============================================================
// k_post: 128 blocks x 256 threads. attended[b,d] = m[b].Wv[d] + bv[d].
// Hoisted Wv loads; m staged in smem; 16 accumulators; one reduce phase.
// ============================================================
__global__ __launch_bounds__(256) void k_post(
    const float* __restrict__ Wv, const float* __restrict__ bv,
    float* __restrict__ attended)
{
    extern __shared__ __align__(16) float4 ms4[];   // [B][256] = 64 KB
    int tid = threadIdx.x;
    int warp = tid >> 5, lane = tid & 31;
    int d = blockIdx.x * 8 + warp;

    const float4* W4 = reinterpret_cast<const float4*>(Wv) + (size_t)d * D4;
    float4 w[8];
#pragma unroll
    for (int ch = 0; ch < 8; ch++) w[ch] = W4[ch * 32 + lane];

    const float4* gm4 = reinterpret_cast<const float4*>(g_m);
    for (int i = tid; i < B * D4; i += 256) ms4[i] = gm4[i];
    __syncthreads();

    float acc[16];
#pragma unroll
    for (int bb = 0; bb < 16; bb++) acc[bb] = 0.f;

#pragma unroll
    for (int ch = 0; ch < 8; ch++) {
#pragma unroll
        for (int bb = 0; bb < 16; bb++) {
            float4 m = ms4[bb * D4 + ch * 32 + lane];
            acc[bb] += m.x * w[ch].x + m.y * w[ch].y
                     + m.z * w[ch].z + m.w * w[ch].w;
        }
    }

#pragma unroll
    for (int o = 16; o > 0; o >>= 1) {
#pragma unroll
        for (int bb = 0; bb < 16; bb++)
            acc[bb] += __shfl_xor_sync(0xffffffffu, acc[bb], o);
    }
    if (lane == 0) {
        float bb_ = bv[d];
#pragma unroll
        for (int bb = 0; bb < 16; bb++)
            attended[bb * D + d] = acc[bb] + bb_;
    }
}

// ============================================================
extern "C" void kernel_launch(void* const* d_in, const int* in_sizes, int n_in,
                              void* d_out, int out_size)
{
    const float* query = (const float*)d_in[0];
    const float* mb    = (const float*)d_in[1];
    const float* ts    = (const float*)d_in[2];
    const float* ct    = (const float*)d_in[3];
    const float* Wq    = (const float*)d_in[4];
    const float* bq    = (const float*)d_in[5];
    const float* Wk    = (const float*)d_in[6];
    const float* bk    = (const float*)d_in[7];
    const float* Wv    = (const float*)d_in[8];
    const float* bv    = (const float*)d_in[9];
    (void)in_sizes; (void)n_in; (void)out_size;

    float* attended = (float*)d_out;            // [16,1024]
    float* attn     = (float*)d_out + B * D;    // [16,4096]

    cudaFuncSetAttribute(k_main, cudaFuncAttributeMaxDynamicSharedMemorySize,
                         SMEM_MAIN);
    cudaFuncSetAttribute(k_post, cudaFuncAttributeMaxDynamicSharedMemorySize,
                         SMEM_POST);

    k_pre<<<256, 256>>>(query, Wq, bk, ts, ct);        // 1: Q parts + u + tw
    k_qbk<<<B, 256>>>(query, bq, bk);                  // 2: qbk scalars
    k_qt<<<128, 128>>>(Wk, bq);                        // 3: qt partials
    k_main<<<NCTA_MAIN, 256, SMEM_MAIN>>>(mb);         // 4: 268 MB pass
    k_mid<<<80, 256>>>(attn);                          // 5: E, m, attn
    k_post<<<128, 256, SMEM_POST>>>(Wv, bv, attended); // 6: attended
}

// round 15
// speedup vs baseline: 1.2546x; 1.0272x over previous
#include <cuda_runtime.h>
#include <cstdint>

// CausalMemoryAttention: B=16, S=4096, D=1024   (exact restructure, validated)
//   Q = query@Wq^T + bq ; qt = Q@Wk ; qbk = query.(Wq^T.bk) + bq.bk
//   score[b,s] = (mb[b,s].qt[b] + qbk[b])/32 * tw[b,s],  tw = exp(-0.01*(ct-ts))
//   p = exp(score); attn = p/E; m = (sum p*mb)/E; attended = m@Wv^T + bv
// 5 launches:
//   k_pre (Q partials + u partials + tw)                          256 blocks
//   k_qk  (qt partials + qbk scalars)                             144 blocks
//   k_main(268MB pass, R4 loop, slim prologue/epilogue; 55us/61%) 288 blocks
//   k_mid (m = sum macc / E)                                       16 blocks
//   k_fin (attended GEMM + attn normalize, independent roles)     192 blocks

#define B 16
#define S 4096
#define D 1024
#define D4 256
#define QT_SPLITS 16
#define U_SPLITS 16
#define CTAS_PER_B 18
#define NCTA_MAIN (B * CTAS_PER_B)        // 288 (single wave at 2 CTA/SM)
#define DEPTH 3
#define STAGE_ROWS 8
#define STAGE_F4 (STAGE_ROWS * D4)        // 2048 float4
#define STAGE_BYTES (STAGE_F4 * 16)       // 32 KB
#define SMEM_MAIN (DEPTH * STAGE_BYTES)   // 96 KB
#define SMEM_FIN (B * D * 4)              // 64 KB (all of m)

// -------- scratch (device globals; no dynamic allocation) --------
__device__ __align__(16) float g_q_part[16 * B * D];     // c-split Q partials
__device__ __align__(16) float g_qt_part[QT_SPLITS * B * D];
__device__ __align__(16) float g_u_part[U_SPLITS * D];
__device__ float g_qbk[B];
__device__ __align__(16) float g_tw[B * S];
__device__ __align__(16) float g_p[B * S];
__device__ __align__(16) float g_macc[NCTA_MAIN * D];
__device__ float g_Epart[NCTA_MAIN];
__device__ __align__(16) float g_m[B * D];

// ---------------- cp.async helpers ----------------
__device__ __forceinline__ void cp_async16(uint32_t smem, const void* gmem) {
    asm volatile("cp.async.cg.shared.global [%0], [%1], 16;"
                 :: "r"(smem), "l"(gmem) : "memory");
}
__device__ __forceinline__ void cp_commit() {
    asm volatile("cp.async.commit_group;" ::: "memory");
}
template <int N> __device__ __forceinline__ void cp_wait() {
    asm volatile("cp.async.wait_group %0;" :: "n"(N) : "memory");
}

// ============================================================
// k_pre: 256 independent blocks x 256 threads. Shuffle-free.
//   bid 0..127 : Q-partial role (d-tile 128, c-chunk 64) -> g_q_part
//   bid 128..191: u-role (e-tile 256, d-chunk 64, MLP 16) -> g_u_part
//   bid 192..255: tw-role.
// ============================================================
__global__ __launch_bounds__(256) void k_pre(
    const float* __restrict__ query, const float* __restrict__ Wq,
    const float* __restrict__ bk,
    const float* __restrict__ ts, const float* __restrict__ ct)
{
    int bid = blockIdx.x, tid = threadIdx.x;

    if (bid < 128) {
        __shared__ float wt[64 * 133];    // wt[c][d_local], pad 133
        __shared__ float qs[16 * 64];     // qs[b][c]
        int dt = bid & 7, cs = bid >> 3;
        int d0 = dt * 128, c0 = cs * 64;

#pragma unroll
        for (int i = 0; i < 32; i++) {
            int row = i * 4 + (tid >> 6);   // d_local 0..127
            int col = tid & 63;             // c_local 0..63
            wt[col * 133 + row] = Wq[(size_t)(d0 + row) * D + c0 + col];
        }
        for (int i = tid; i < 1024; i += 256) {
            int b = i >> 6, c = i & 63;
            qs[b * 64 + c] = query[b * D + c0 + c];
        }
        __syncthreads();

        int dl = tid & 127;
        int bh = tid >> 7;                  // 0/1 -> batches 0..7 / 8..15
        float acc[8];
#pragma unroll
        for (int bb = 0; bb < 8; bb++) acc[bb] = 0.f;
#pragma unroll 4
        for (int c = 0; c < 64; c++) {
            float wv = wt[c * 133 + dl];
#pragma unroll
            for (int bb = 0; bb < 8; bb++)
                acc[bb] += qs[(bh * 8 + bb) * 64 + c] * wv;
        }
#pragma unroll
        for (int bb = 0; bb < 8; bb++)
            g_q_part[(size_t)cs * (B * D) + (bh * 8 + bb) * D + d0 + dl] = acc[bb];
    } else if (bid < 192) {
        // u-role: u[e] partial over 64 d's, unroll 16 (MLP 16)
        int q = bid - 128;
        int e = (q & 3) * 256 + tid;
        int dp = q >> 2;                    // 0..15
        int dbase = dp * 64;
        float s = 0.f;
#pragma unroll 16
        for (int d = 0; d < 64; d++)
            s += Wq[(size_t)(dbase + d) * D + e] * bk[dbase + d];
        g_u_part[dp * D + e] = s;
    } else {
        // tw-role
        int idx = (bid - 192) * 1024 + tid * 4;
        int b = idx >> 12;
        float curt = ct[b];
        float4 t = *reinterpret_cast<const float4*>(ts + idx);
        float4 w;
        w.x = __expf(-0.01f * (curt - t.x));
        w.y = __expf(-0.01f * (curt - t.y));
        w.z = __expf(-0.01f * (curt - t.z));
        w.w = __expf(-0.01f * (curt - t.w));
        *reinterpret_cast<float4*>(g_tw + idx) = w;
    }
}

// ============================================================
// k_qk: 144 blocks x 128 threads.
//   bid 0..127 : qt-role (e-tile 128, d-chunk 64): Q reduce+bias fold
//                into smem, then 64x16 FMA vs coalesced Wk.
//   bid 128..143: qbk-role for b = bid-128:
//                qbk[b] = query[b].u + bq.bk (u summed from 16 partials).
// ============================================================
__global__ __launch_bounds__(128) void k_qk(
    const float* __restrict__ Wk, const float* __restrict__ bq,
    const float* __restrict__ query, const float* __restrict__ bk)
{
    __shared__ float Qs[64 * 20];      // qt-role: Qs[dl][b], pad 20
    __shared__ float sW[4];            // qbk-role warp sums
    int bid = blockIdx.x, tid = threadIdx.x;

    if (bid < 128) {
        int et = bid & 7, by = bid >> 3;
        int e = et * 128 + tid;
        int d0 = by * 64;

        for (int i = tid; i < 1024; i += 128) {
            int dl = i & 63, b = i >> 6;
            float s = bq[d0 + dl];
#pragma unroll
            for (int sp = 0; sp < 16; sp++)
                s += g_q_part[(size_t)sp * (B * D) + b * D + d0 + dl];
            Qs[dl * 20 + b] = s;
        }
        __syncthreads();

        float acc[16];
#pragma unroll
        for (int bb = 0; bb < 16; bb++) acc[bb] = 0.f;
#pragma unroll 8
        for (int dl = 0; dl < 64; dl++) {
            float wv = Wk[(size_t)(d0 + dl) * D + e];
            const float4* q4 = reinterpret_cast<const float4*>(&Qs[dl * 20]);
#pragma unroll
            for (int j = 0; j < 4; j++) {
                float4 qq = q4[j];
                acc[4 * j + 0] += qq.x * wv;
                acc[4 * j + 1] += qq.y * wv;
                acc[4 * j + 2] += qq.z * wv;
                acc[4 * j + 3] += qq.w * wv;
            }
        }
#pragma unroll
        for (int bb = 0; bb < 16; bb++)
            g_qt_part[(size_t)(by * 16 + bb) * D + e] = acc[bb];
    } else {
        int b = bid - 128;
        int warp = tid >> 5, lane = tid & 31;
        const float4* U4 = reinterpret_cast<const float4*>(g_u_part);
        const float4* X4 = reinterpret_cast<const float4*>(query) + b * D4;
        const float4* bq4 = reinterpret_cast<const float4*>(bq);
        const float4* bk4 = reinterpret_cast<const float4*>(bk);

        float s = 0.f;
#pragma unroll
        for (int h = 0; h < 2; h++) {
            int idx = h * 128 + tid;       // covers all 256 float4 once
            float4 u = U4[idx];
#pragma unroll
            for (int sp = 1; sp < U_SPLITS; sp++) {
                float4 up = U4[sp * D4 + idx];
                u.x += up.x; u.y += up.y; u.z += up.z; u.w += up.w;
            }
            float4 x = X4[idx];
            s += x.x * u.x + x.y * u.y + x.z * u.z + x.w * u.w;
            float4 a = bq4[idx], c = bk4[idx];
            s += a.x * c.x + a.y * c.y + a.z * c.z + a.w * c.w;
        }
#pragma unroll
        for (int o = 16; o > 0; o >>= 1) s += __shfl_xor_sync(0xffffffffu, s, o);
        if (lane == 0) sW[warp] = s;
        __syncthreads();
        if (tid == 0) g_qbk[b] = sW[0] + sW[1] + sW[2] + sW[3];
    }
}

// ============================================================
// k_main: streaming pass over memory_bank. FROZEN (R14-validated:
// 55.0us @ 61% DRAM, regs 118, no spills). R4 loop, slim prologue
// (qt reduce + qbk scalar), slim epilogue (macc/Epart only).
// ============================================================
__global__ __launch_bounds__(256, 2) void k_main(
    const float* __restrict__ mb)
{
    extern __shared__ __align__(16) float4 sbuf[];   // DEPTH * STAGE_F4
    __shared__ float sE[8];

    int b = blockIdx.x / CTAS_PER_B;
    int j = blockIdx.x % CTAS_PER_B;
    int warp = threadIdx.x >> 5, lane = threadIdx.x & 31, tid = threadIdx.x;

    // 512 stages per batch split 8x29 + 10x28
    int nst = (j < 8) ? 29 : 28;
    int st0 = (j < 8) ? j * 29 : 232 + (j - 8) * 28;

    const float* gsrc = mb + (size_t)b * S * D + (size_t)st0 * STAGE_ROWS * D;
    uint32_t sb = (uint32_t)__cvta_generic_to_shared(sbuf);

    // ---- prologue: issue first DEPTH stages ----
    int issued = 0;
    for (; issued < DEPTH && issued < nst; issued++) {
        uint32_t dst = sb + (uint32_t)(issued % DEPTH) * STAGE_BYTES;
        const float* src = gsrc + (size_t)issued * STAGE_ROWS * D;
        for (int c = tid; c < STAGE_F4; c += 256)
            cp_async16(dst + (uint32_t)c * 16, src + (size_t)c * 4);
        cp_commit();
    }

    // ---- qt split-reduce (overlaps DRAM ramp) + qbk scalar ----
    float4 q[8];
#pragma unroll
    for (int k = 0; k < 8; k++) q[k] = make_float4(0.f, 0.f, 0.f, 0.f);
    for (int sp = 0; sp < QT_SPLITS; sp++) {
        const float4* qp = reinterpret_cast<const float4*>(g_qt_part)
                           + (size_t)(sp * B + b) * D4;
#pragma unroll
        for (int k = 0; k < 8; k++) {
            float4 v = qp[k * 32 + lane];
            q[k].x += v.x; q[k].y += v.y; q[k].z += v.z; q[k].w += v.w;
        }
    }
    float qb = g_qbk[b];

    float4 acc[8];
#pragma unroll
    for (int k = 0; k < 8; k++) acc[k] = make_float4(0.f, 0.f, 0.f, 0.f);
    float Ew = 0.f;

    // ---- mainloop (R4-validated): wait<2> / sync / read / sync / refill ----
    for (int i = 0; i < nst; i++) {
        int s = (st0 + i) * STAGE_ROWS + warp;
        float twv = g_tw[b * S + s];          // off the critical chain

        if (issued < nst) cp_wait<DEPTH - 1>(); else cp_wait<0>();
        __syncthreads();

        const float4* vp = sbuf + ((size_t)(i % DEPTH) * STAGE_ROWS + warp) * D4;
        float4 v[8];
#pragma unroll
        for (int k = 0; k < 8; k++) v[k] = vp[k * 32 + lane];
        __syncthreads();                 // slot consumed -> free for refill

        // refill the freed slot BEFORE the long compute chain
        if (issued < nst) {
            uint32_t dst = sb + (uint32_t)(issued % DEPTH) * STAGE_BYTES;
            const float* src = gsrc + (size_t)issued * STAGE_ROWS * D;
            for (int c = tid; c < STAGE_F4; c += 256)
                cp_async16(dst + (uint32_t)c * 16, src + (size_t)c * 4);
            cp_commit();
            issued++;
        }

        float d0 = 0.f, d1 = 0.f, d2 = 0.f, d3 = 0.f;
#pragma unroll
        for (int k = 0; k < 8; k++) {
            d0 += v[k].x * q[k].x; d1 += v[k].y * q[k].y;
            d2 += v[k].z * q[k].z; d3 += v[k].w * q[k].w;
        }
        float ds = (d0 + d1) + (d2 + d3);
#pragma unroll
        for (int o = 16; o > 0; o >>= 1) ds += __shfl_xor_sync(0xffffffffu, ds, o);

        float p = __expf((ds + qb) * 0.03125f * twv);
        if (lane == 0) g_p[b * S + s] = p;
        Ew += p;
#pragma unroll
        for (int k = 0; k < 8; k++) {
            acc[k].x += p * v[k].x; acc[k].y += p * v[k].y;
            acc[k].z += p * v[k].z; acc[k].w += p * v[k].w;
        }
    }

    // ---- epilogue (R4): cross-warp reduce, write macc/Epart, exit ----
    cp_wait<0>();
    __syncthreads();
    float4* red = sbuf;
#pragma unroll
    for (int k = 0; k < 8; k++)
        red[(size_t)warp * D4 + k * 32 + lane] = acc[k];
    if (lane == 0) sE[warp] = Ew;
    __syncthreads();

    float4 r = red[tid];
#pragma unroll
    for (int w = 1; w < 8; w++) {
        float4 v = red[(size_t)w * D4 + tid];
        r.x += v.x; r.y += v.y; r.z += v.z; r.w += v.w;
    }
    reinterpret_cast<float4*>(g_macc)[(size_t)blockIdx.x * D4 + tid] = r;
    if (tid == 0) {
        float e = 0.f;
#pragma unroll
        for (int w = 0; w < 8; w++) e += sE[w];
        g_Epart[blockIdx.x] = e;
    }
}

// ============================================================
// k_mid: 16 blocks x 256 threads. m[b] = (sum_c macc[b,c]) / E.
// ============================================================
__global__ __launch_bounds__(256) void k_mid()
{
    __shared__ float sInv;
    int b = blockIdx.x;
    int tid = threadIdx.x, lane = tid & 31;

    if (tid < 32) {
        float e = (lane < CTAS_PER_B) ? g_Epart[b * CTAS_PER_B + lane] : 0.f;
#pragma unroll
        for (int o = 16; o > 0; o >>= 1) e += __shfl_xor_sync(0xffffffffu, e, o);
        if (lane == 0) sInv = 1.f / e;
    }
    __syncthreads();
    float inv = sInv;

    const float4* mp = reinterpret_cast<const float4*>(g_macc);
    float4 a = make_float4(0.f, 0.f, 0.f, 0.f);
#pragma unroll
    for (int c = 0; c < CTAS_PER_B; c++) {
        float4 v = mp[(size_t)(b * CTAS_PER_B + c) * D4 + tid];
        a.x += v.x; a.y += v.y; a.z += v.z; a.w += v.w;
    }
    a.x *= inv; a.y *= inv; a.z *= inv; a.w *= inv;
    reinterpret_cast<float4*>(g_m)[b * D4 + tid] = a;
}

// ============================================================
// k_fin: 192 blocks x 256 threads.
//   bid 0..127 : attended role — attended[b,d] = m[b].Wv[d] + bv[d].
//     Hoisted Wv loads, m staged in smem, 16 accumulators, one reduce.
//   bid 128..191: attn role — b=(bid-128)>>2, quarter=(bid-128)&3:
//     inv = 1/E (redundant warp-reduce of 18 Epart), attn = p*inv.
//     Depends only on k_main outputs -> runs concurrent with attended.
// ============================================================
__global__ __launch_bounds__(256) void k_fin(
    const float* __restrict__ Wv, const float* __restrict__ bv,
    float* __restrict__ attended, float* __restrict__ attn)
{
    extern __shared__ __align__(16) float4 ms4[];   // [B][256] = 64 KB
    __shared__ float sInv;
    int bid = blockIdx.x, tid = threadIdx.x;

    if (bid < 128) {
        int warp = tid >> 5, lane = tid & 31;
        int d = bid * 8 + warp;

        const float4* W4 = reinterpret_cast<const float4*>(Wv) + (size_t)d * D4;
        float4 w[8];
#pragma unroll
        for (int ch = 0; ch < 8; ch++) w[ch] = W4[ch * 32 + lane];

        const float4* gm4 = reinterpret_cast<const float4*>(g_m);
        for (int i = tid; i < B * D4; i += 256) ms4[i] = gm4[i];
        __syncthreads();

        float acc[16];
#pragma unroll
        for (int bb = 0; bb < 16; bb++) acc[bb] = 0.f;

#pragma unroll
        for (int ch = 0; ch < 8; ch++) {
#pragma unroll
            for (int bb = 0; bb < 16; bb++) {
                float4 m = ms4[bb * D4 + ch * 32 + lane];
                acc[bb] += m.x * w[ch].x + m.y * w[ch].y
                         + m.z * w[ch].z + m.w * w[ch].w;
            }
        }

#pragma unroll
        for (int o = 16; o > 0; o >>= 1) {
#pragma unroll
            for (int bb = 0; bb < 16; bb++)
                acc[bb] += __shfl_xor_sync(0xffffffffu, acc[bb], o);
        }
        if (lane == 0) {
            float bb_ = bv[d];
#pragma unroll
            for (int bb = 0; bb < 16; bb++)
                attended[bb * D + d] = acc[bb] + bb_;
        }
    } else {
        int q = bid - 128;
        int b = q >> 2, quarter = q & 3;
        int lane = tid & 31;

        if (tid < 32) {
            float e = (lane < CTAS_PER_B) ? g_Epart[b * CTAS_PER_B + lane] : 0.f;
#pragma unroll
            for (int o = 16; o > 0; o >>= 1)
                e += __shfl_xor_sync(0xffffffffu, e, o);
            if (lane == 0) sInv = 1.f / e;
        }
        __syncthreads();
        float inv = sInv;

        int s = quarter * 1024 + tid * 4;
        float4 p = *reinterpret_cast<const float4*>(g_p + b * S + s);
        p.x *= inv; p.y *= inv; p.z *= inv; p.w *= inv;
        *reinterpret_cast<float4*>(attn + b * S + s) = p;
    }
}

// ============================================================
extern "C" void kernel_launch(void* const* d_in, const int* in_sizes, int n_in,
                              void* d_out, int out_size)
{
    const float* query = (const float*)d_in[0];
    const float* mb    = (const float*)d_in[1];
    const float* ts    = (const float*)d_in[2];
    const float* ct    = (const float*)d_in[3];
    const float* Wq    = (const float*)d_in[4];
    const float* bq    = (const float*)d_in[5];
    const float* Wk    = (const float*)d_in[6];
    const float* bk    = (const float*)d_in[7];
    const float* Wv    = (const float*)d_in[8];
    const float* bv    = (const float*)d_in[9];
    (void)in_sizes; (void)n_in; (void)out_size;

    float* attended = (float*)d_out;            // [16,1024]
    float* attn     = (float*)d_out + B * D;    // [16,4096]

    cudaFuncSetAttribute(k_main, cudaFuncAttributeMaxDynamicSharedMemorySize,
                         SMEM_MAIN);
    cudaFuncSetAttribute(k_fin, cudaFuncAttributeMaxDynamicSharedMemorySize,
                         SMEM_FIN);

    k_pre<<<256, 256>>>(query, Wq, bk, ts, ct);        // 1: Q parts + u + tw
    k_qk<<<144, 128>>>(Wk, bq, query, bk);             // 2: qt partials + qbk
    k_main<<<NCTA_MAIN, 256, SMEM_MAIN>>>(mb);         // 3: 268 MB pass
    k_mid<<<B, 256>>>();                               // 4: m finalize
    k_fin<<<192, 256, SMEM_FIN>>>(Wv, bv, attended, attn); // 5: attended+attn
}

// round 16
// speedup vs baseline: 1.2551x; 1.0004x over previous
#include <cuda_runtime.h>
#include <cstdint>

// CausalMemoryAttention: B=16, S=4096, D=1024   (exact restructure, validated)
//   Q = query@Wq^T + bq ; qt = Q@Wk ; qbk = Q.bk (from Q partials directly)
//   score[b,s] = (mb[b,s].qt[b] + qbk[b])/32 * tw[b,s],  tw = exp(-0.01*(ct-ts))
//   p = exp(score); attn = p/E; m = (sum p*mb)/E; attended = m@Wv^T + bv
// 5 launches:
//   k_pre (Q partials + tw)                                       192 blocks
//   k_qk  (qt partials + qbk from Q partials)                     144 blocks
//   k_main(268MB pass, R4 loop, slim prologue/epilogue; 55us/61%) 288 blocks
//   k_mid (m finalize + attn normalize, no dyn smem)               80 blocks
//   k_fin (attended GEMM only)                                    128 blocks

#define B 16
#define S 4096
#define D 1024
#define D4 256
#define QT_SPLITS 16
#define CTAS_PER_B 18
#define NCTA_MAIN (B * CTAS_PER_B)        // 288 (single wave at 2 CTA/SM)
#define DEPTH 3
#define STAGE_ROWS 8
#define STAGE_F4 (STAGE_ROWS * D4)        // 2048 float4
#define STAGE_BYTES (STAGE_F4 * 16)       // 32 KB
#define SMEM_MAIN (DEPTH * STAGE_BYTES)   // 96 KB
#define SMEM_FIN (B * D * 4)              // 64 KB (all of m)

// -------- scratch (device globals; no dynamic allocation) --------
__device__ __align__(16) float g_q_part[16 * B * D];     // c-split Q partials
__device__ __align__(16) float g_qt_part[QT_SPLITS * B * D];
__device__ float g_qbk[B];
__device__ __align__(16) float g_tw[B * S];
__device__ __align__(16) float g_p[B * S];
__device__ __align__(16) float g_macc[NCTA_MAIN * D];
__device__ float g_Epart[NCTA_MAIN];
__device__ __align__(16) float g_m[B * D];

// ---------------- cp.async helpers ----------------
__device__ __forceinline__ void cp_async16(uint32_t smem, const void* gmem) {
    asm volatile("cp.async.cg.shared.global [%0], [%1], 16;"
                 :: "r"(smem), "l"(gmem) : "memory");
}
__device__ __forceinline__ void cp_commit() {
    asm volatile("cp.async.commit_group;" ::: "memory");
}
template <int N> __device__ __forceinline__ void cp_wait() {
    asm volatile("cp.async.wait_group %0;" :: "n"(N) : "memory");
}

// ============================================================
// k_pre: 192 independent blocks x 256 threads. Shuffle-free.
//   bid 0..127 : Q-partial role (d-tile 128, c-chunk 64) -> g_q_part
//   bid 128..191: tw-role.
// ============================================================
__global__ __launch_bounds__(256) void k_pre(
    const float* __restrict__ query, const float* __restrict__ Wq,
    const float* __restrict__ ts, const float* __restrict__ ct)
{
    int bid = blockIdx.x, tid = threadIdx.x;

    if (bid < 128) {
        __shared__ float wt[64 * 133];    // wt[c][d_local], pad 133
        __shared__ float qs[16 * 64];     // qs[b][c]
        int dt = bid & 7, cs = bid >> 3;
        int d0 = dt * 128, c0 = cs * 64;

#pragma unroll
        for (int i = 0; i < 32; i++) {
            int row = i * 4 + (tid >> 6);   // d_local 0..127
            int col = tid & 63;             // c_local 0..63
            wt[col * 133 + row] = Wq[(size_t)(d0 + row) * D + c0 + col];
        }
        for (int i = tid; i < 1024; i += 256) {
            int b = i >> 6, c = i & 63;
            qs[b * 64 + c] = query[b * D + c0 + c];
        }
        __syncthreads();

        int dl = tid & 127;
        int bh = tid >> 7;                  // 0/1 -> batches 0..7 / 8..15
        float acc[8];
#pragma unroll
        for (int bb = 0; bb < 8; bb++) acc[bb] = 0.f;
#pragma unroll 4
        for (int c = 0; c < 64; c++) {
            float wv = wt[c * 133 + dl];
#pragma unroll
            for (int bb = 0; bb < 8; bb++)
                acc[bb] += qs[(bh * 8 + bb) * 64 + c] * wv;
        }
#pragma unroll
        for (int bb = 0; bb < 8; bb++)
            g_q_part[(size_t)cs * (B * D) + (bh * 8 + bb) * D + d0 + dl] = acc[bb];
    } else {
        // tw-role
        int idx = (bid - 128) * 1024 + tid * 4;
        int b = idx >> 12;
        float curt = ct[b];
        float4 t = *reinterpret_cast<const float4*>(ts + idx);
        float4 w;
        w.x = __expf(-0.01f * (curt - t.x));
        w.y = __expf(-0.01f * (curt - t.y));
        w.z = __expf(-0.01f * (curt - t.z));
        w.w = __expf(-0.01f * (curt - t.w));
        *reinterpret_cast<float4*>(g_tw + idx) = w;
    }
}

// ============================================================
// k_qk: 144 blocks x 128 threads.
//   bid 0..127 : qt-role (e-tile 128, d-chunk 64): Q reduce+bias fold
//                into smem, then 64x16 FMA vs coalesced Wk.
//   bid 128..143: qbk-role for b = bid-128:
//                qbk[b] = sum_d (bq[d] + sum_sp q_part[sp][b][d]) * bk[d]
// ============================================================
__global__ __launch_bounds__(128) void k_qk(
    const float* __restrict__ Wk, const float* __restrict__ bq,
    const float* __restrict__ bk)
{
    __shared__ float Qs[64 * 20];      // qt-role: Qs[dl][b], pad 20
    __shared__ float sW[4];            // qbk-role warp sums
    int bid = blockIdx.x, tid = threadIdx.x;

    if (bid < 128) {
        int et = bid & 7, by = bid >> 3;
        int e = et * 128 + tid;
        int d0 = by * 64;

        for (int i = tid; i < 1024; i += 128) {
            int dl = i & 63, b = i >> 6;
            float s = bq[d0 + dl];
#pragma unroll
            for (int sp = 0; sp < 16; sp++)
                s += g_q_part[(size_t)sp * (B * D) + b * D + d0 + dl];
            Qs[dl * 20 + b] = s;
        }
        __syncthreads();

        float acc[16];
#pragma unroll
        for (int bb = 0; bb < 16; bb++) acc[bb] = 0.f;
#pragma unroll 8
        for (int dl = 0; dl < 64; dl++) {
            float wv = Wk[(size_t)(d0 + dl) * D + e];
            const float4* q4 = reinterpret_cast<const float4*>(&Qs[dl * 20]);
#pragma unroll
            for (int j = 0; j < 4; j++) {
                float4 qq = q4[j];
                acc[4 * j + 0] += qq.x * wv;
                acc[4 * j + 1] += qq.y * wv;
                acc[4 * j + 2] += qq.z * wv;
                acc[4 * j + 3] += qq.w * wv;
            }
        }
#pragma unroll
        for (int bb = 0; bb < 16; bb++)
            g_qt_part[(size_t)(by * 16 + bb) * D + e] = acc[bb];
    } else {
        int b = bid - 128;
        int warp = tid >> 5, lane = tid & 31;

        float s = 0.f;
#pragma unroll
        for (int k = 0; k < 8; k++) {
            int d = k * 128 + tid;
            float qv = bq[d];
#pragma unroll
            for (int sp = 0; sp < 16; sp++)
                qv += g_q_part[(size_t)sp * (B * D) + b * D + d];
            s += qv * bk[d];
        }
#pragma unroll
        for (int o = 16; o > 0; o >>= 1) s += __shfl_xor_sync(0xffffffffu, s, o);
        if (lane == 0) sW[warp] = s;
        __syncthreads();
        if (tid == 0) g_qbk[b] = sW[0] + sW[1] + sW[2] + sW[3];
    }
}

// ============================================================
// k_main: streaming pass over memory_bank. FROZEN (R14-validated:
// 55.0us @ 61% DRAM, regs 118, no spills). R4 loop, slim prologue
// (qt reduce + qbk scalar), slim epilogue (macc/Epart only).
// ============================================================
__global__ __launch_bounds__(256, 2) void k_main(
    const float* __restrict__ mb)
{
    extern __shared__ __align__(16) float4 sbuf[];   // DEPTH * STAGE_F4
    __shared__ float sE[8];

    int b = blockIdx.x / CTAS_PER_B;
    int j = blockIdx.x % CTAS_PER_B;
    int warp = threadIdx.x >> 5, lane = threadIdx.x & 31, tid = threadIdx.x;

    // 512 stages per batch split 8x29 + 10x28
    int nst = (j < 8) ? 29 : 28;
    int st0 = (j < 8) ? j * 29 : 232 + (j - 8) * 28;

    const float* gsrc = mb + (size_t)b * S * D + (size_t)st0 * STAGE_ROWS * D;
    uint32_t sb = (uint32_t)__cvta_generic_to_shared(sbuf);

    // ---- prologue: issue first DEPTH stages ----
    int issued = 0;
    for (; issued < DEPTH && issued < nst; issued++) {
        uint32_t dst = sb + (uint32_t)(issued % DEPTH) * STAGE_BYTES;
        const float* src = gsrc + (size_t)issued * STAGE_ROWS * D;
        for (int c = tid; c < STAGE_F4; c += 256)
            cp_async16(dst + (uint32_t)c * 16, src + (size_t)c * 4);
        cp_commit();
    }

    // ---- qt split-reduce (overlaps DRAM ramp) + qbk scalar ----
    float4 q[8];
#pragma unroll
    for (int k = 0; k < 8; k++) q[k] = make_float4(0.f, 0.f, 0.f, 0.f);
    for (int sp = 0; sp < QT_SPLITS; sp++) {
        const float4* qp = reinterpret_cast<const float4*>(g_qt_part)
                           + (size_t)(sp * B + b) * D4;
#pragma unroll
        for (int k = 0; k < 8; k++) {
            float4 v = qp[k * 32 + lane];
            q[k].x += v.x; q[k].y += v.y; q[k].z += v.z; q[k].w += v.w;
        }
    }
    float qb = g_qbk[b];

    float4 acc[8];
#pragma unroll
    for (int k = 0; k < 8; k++) acc[k] = make_float4(0.f, 0.f, 0.f, 0.f);
    float Ew = 0.f;

    // ---- mainloop (R4-validated): wait<2> / sync / read / sync / refill ----
    for (int i = 0; i < nst; i++) {
        int s = (st0 + i) * STAGE_ROWS + warp;
        float twv = g_tw[b * S + s];          // off the critical chain

        if (issued < nst) cp_wait<DEPTH - 1>(); else cp_wait<0>();
        __syncthreads();

        const float4* vp = sbuf + ((size_t)(i % DEPTH) * STAGE_ROWS + warp) * D4;
        float4 v[8];
#pragma unroll
        for (int k = 0; k < 8; k++) v[k] = vp[k * 32 + lane];
        __syncthreads();                 // slot consumed -> free for refill

        // refill the freed slot BEFORE the long compute chain
        if (issued < nst) {
            uint32_t dst = sb + (uint32_t)(issued % DEPTH) * STAGE_BYTES;
            const float* src = gsrc + (size_t)issued * STAGE_ROWS * D;
            for (int c = tid; c < STAGE_F4; c += 256)
                cp_async16(dst + (uint32_t)c * 16, src + (size_t)c * 4);
            cp_commit();
            issued++;
        }

        float d0 = 0.f, d1 = 0.f, d2 = 0.f, d3 = 0.f;
#pragma unroll
        for (int k = 0; k < 8; k++) {
            d0 += v[k].x * q[k].x; d1 += v[k].y * q[k].y;
            d2 += v[k].z * q[k].z; d3 += v[k].w * q[k].w;
        }
        float ds = (d0 + d1) + (d2 + d3);
#pragma unroll
        for (int o = 16; o > 0; o >>= 1) ds += __shfl_xor_sync(0xffffffffu, ds, o);

        float p = __expf((ds + qb) * 0.03125f * twv);
        if (lane == 0) g_p[b * S + s] = p;
        Ew += p;
#pragma unroll
        for (int k = 0; k < 8; k++) {
            acc[k].x += p * v[k].x; acc[k].y += p * v[k].y;
            acc[k].z += p * v[k].z; acc[k].w += p * v[k].w;
        }
    }

    // ---- epilogue (R4): cross-warp reduce, write macc/Epart, exit ----
    cp_wait<0>();
    __syncthreads();
    float4* red = sbuf;
#pragma unroll
    for (int k = 0; k < 8; k++)
        red[(size_t)warp * D4 + k * 32 + lane] = acc[k];
    if (lane == 0) sE[warp] = Ew;
    __syncthreads();

    float4 r = red[tid];
#pragma unroll
    for (int w = 1; w < 8; w++) {
        float4 v = red[(size_t)w * D4 + tid];
        r.x += v.x; r.y += v.y; r.z += v.z; r.w += v.w;
    }
    reinterpret_cast<float4*>(g_macc)[(size_t)blockIdx.x * D4 + tid] = r;
    if (tid == 0) {
        float e = 0.f;
#pragma unroll
        for (int w = 0; w < 8; w++) e += sE[w];
        g_Epart[blockIdx.x] = e;
    }
}

// ============================================================
// k_mid: 80 blocks x 256 threads, NO dynamic smem.
//   bid 0..15 : m-role — m[b] = (sum_c macc[b,c]) / E.
//   bid 16..79: attn-role — b=(bid-16)>>2, quarter=(bid-16)&3:
//               inv = 1/E (redundant warp-reduce), attn = p*inv.
// Both roles depend only on k_main outputs.
// ============================================================
__global__ __launch_bounds__(256) void k_mid(float* __restrict__ attn)
{
    __shared__ float sInv;
    int bid = blockIdx.x;
    int tid = threadIdx.x, lane = tid & 31;

    if (bid < 16) {
        int b = bid;
        if (tid < 32) {
            float e = (lane < CTAS_PER_B) ? g_Epart[b * CTAS_PER_B + lane] : 0.f;
#pragma unroll
            for (int o = 16; o > 0; o >>= 1)
                e += __shfl_xor_sync(0xffffffffu, e, o);
            if (lane == 0) sInv = 1.f / e;
        }
        __syncthreads();
        float inv = sInv;

        const float4* mp = reinterpret_cast<const float4*>(g_macc);
        float4 a = make_float4(0.f, 0.f, 0.f, 0.f);
#pragma unroll
        for (int c = 0; c < CTAS_PER_B; c++) {
            float4 v = mp[(size_t)(b * CTAS_PER_B + c) * D4 + tid];
            a.x += v.x; a.y += v.y; a.z += v.z; a.w += v.w;
        }
        a.x *= inv; a.y *= inv; a.z *= inv; a.w *= inv;
        reinterpret_cast<float4*>(g_m)[b * D4 + tid] = a;
    } else {
        int q = bid - 16;
        int b = q >> 2, quarter = q & 3;

        if (tid < 32) {
            float e = (lane < CTAS_PER_B) ? g_Epart[b * CTAS_PER_B + lane] : 0.f;
#pragma unroll
            for (int o = 16; o > 0; o >>= 1)
                e += __shfl_xor_sync(0xffffffffu, e, o);
            if (lane == 0) sInv = 1.f / e;
        }
        __syncthreads();
        float inv = sInv;

        int s = quarter * 1024 + tid * 4;
        float4 p = *reinterpret_cast<const float4*>(g_p + b * S + s);
        p.x *= inv; p.y *= inv; p.z *= inv; p.w *= inv;
        *reinterpret_cast<float4*>(attn + b * S + s) = p;
    }
}

// ============================================================
// k_fin: 128 blocks x 256 threads. attended[b,d] = m[b].Wv[d] + bv[d].
// Hoisted Wv loads; m staged in smem; 16 accumulators; one reduce phase.
// ============================================================
__global__ __launch_bounds__(256) void k_fin(
    const float* __restrict__ Wv, const float* __restrict__ bv,
    float* __restrict__ attended)
{
    extern __shared__ __align__(16) float4 ms4[];   // [B][256] = 64 KB
    int tid = threadIdx.x;
    int warp = tid >> 5, lane = tid & 31;
    int d = blockIdx.x * 8 + warp;

    const float4* W4 = reinterpret_cast<const float4*>(Wv) + (size_t)d * D4;
    float4 w[8];
#pragma unroll
    for (int ch = 0; ch < 8; ch++) w[ch] = W4[ch * 32 + lane];

    const float4* gm4 = reinterpret_cast<const float4*>(g_m);
    for (int i = tid; i < B * D4; i += 256) ms4[i] = gm4[i];
    __syncthreads();

    float acc[16];
#pragma unroll
    for (int bb = 0; bb < 16; bb++) acc[bb] = 0.f;

#pragma unroll
    for (int ch = 0; ch < 8; ch++) {
#pragma unroll
        for (int bb = 0; bb < 16; bb++) {
            float4 m = ms4[bb * D4 + ch * 32 + lane];
            acc[bb] += m.x * w[ch].x + m.y * w[ch].y
                     + m.z * w[ch].z + m.w * w[ch].w;
        }
    }

#pragma unroll
    for (int o = 16; o > 0; o >>= 1) {
#pragma unroll
        for (int bb = 0; bb < 16; bb++)
            acc[bb] += __shfl_xor_sync(0xffffffffu, acc[bb], o);
    }
    if (lane == 0) {
        float bb_ = bv[d];
#pragma unroll
        for (int bb = 0; bb < 16; bb++)
            attended[bb * D + d] = acc[bb] + bb_;
    }
}

// ============================================================
extern "C" void kernel_launch(void* const* d_in, const int* in_sizes, int n_in,
                              void* d_out, int out_size)
{
    const float* query = (const float*)d_in[0];
    const float* mb    = (const float*)d_in[1];
    const float* ts    = (const float*)d_in[2];
    const float* ct    = (const float*)d_in[3];
    const float* Wq    = (const float*)d_in[4];
    const float* bq    = (const float*)d_in[5];
    const float* Wk    = (const float*)d_in[6];
    const float* bk    = (const float*)d_in[7];
    const float* Wv    = (const float*)d_in[8];
    const float* bv    = (const float*)d_in[9];
    (void)in_sizes; (void)n_in; (void)out_size;

    float* attended = (float*)d_out;            // [16,1024]
    float* attn     = (float*)d_out + B * D;    // [16,4096]

    cudaFuncSetAttribute(k_main, cudaFuncAttributeMaxDynamicSharedMemorySize,
                         SMEM_MAIN);
    cudaFuncSetAttribute(k_fin, cudaFuncAttributeMaxDynamicSharedMemorySize,
                         SMEM_FIN);

    k_pre<<<192, 256>>>(query, Wq, ts, ct);            // 1: Q parts + tw
    k_qk<<<144, 128>>>(Wk, bq, bk);                    // 2: qt partials + qbk
    k_main<<<NCTA_MAIN, 256, SMEM_MAIN>>>(mb);         // 3: 268 MB pass
    k_mid<<<80, 256>>>(attn);                          // 4: m + attn
    k_fin<<<128, 256, SMEM_FIN>>>(Wv, bv, attended);   // 5: attended
}